// round 2
// baseline (speedup 1.0000x reference)
#include <cuda_runtime.h>

#define NROW 8192
#define D 128
#define NPAIR 3
#define SP_CAP 32768
#define EPS_STAB 1e-8f

// ---------------- device globals (scratch; no allocs allowed) ----------------
__device__ float g_x2[NROW], g_y2[NROW], g_x28[NROW], g_y28[NROW];
__device__ float g_dk_diag[NPAIR][NROW];
__device__ float g_dkc_diag[NPAIR][NROW];
__device__ int   g_sp_cnt[NPAIR];
__device__ int   g_sp_i[NPAIR][SP_CAP];
__device__ int   g_sp_j[NPAIR][SP_CAP];
__device__ float g_sp_dk[NPAIR][SP_CAP];
__device__ float g_sp_dkc[NPAIR][SP_CAP];
__device__ float g_u[NPAIR][NROW], g_v[NPAIR][NROW], g_acc[NPAIR][NROW];
__device__ float g_scal[NPAIR][5];   // su, sv, u.x2, v.y2, diag cost
__device__ float g_PQ[6][D];         // X^T u / Y^T v per pairing

// ---------------- init: zero scratch ----------------
__global__ void k_init() {
    int t = blockIdx.x * blockDim.x + threadIdx.x;
    int tot = blockDim.x * gridDim.x;
    float* dk  = &g_dk_diag[0][0];
    float* dkc = &g_dkc_diag[0][0];
    for (int i = t; i < NPAIR * NROW; i += tot) { dk[i] = 0.f; dkc[i] = 0.f; }
    float* pq = &g_PQ[0][0];
    for (int i = t; i < 6 * D; i += tot) pq[i] = 0.f;
    if (t < NPAIR) g_sp_cnt[t] = 0;
}

// ---------------- row norms (full 128 and first-8) ----------------
__global__ void k_norms(const float* __restrict__ X, const float* __restrict__ Y) {
    int w = (blockIdx.x * blockDim.x + threadIdx.x) >> 5;
    int lane = threadIdx.x & 31;
    if (w >= 2 * NROW) return;
    const float* M = (w < NROW) ? X : Y;
    int r = (w < NROW) ? w : (w - NROW);
    float4 a = reinterpret_cast<const float4*>(M + (size_t)r * D)[lane];
    float s = a.x * a.x + a.y * a.y + a.z * a.z + a.w * a.w;
    float s8 = (lane < 2) ? s : 0.f;
#pragma unroll
    for (int o = 16; o; o >>= 1) {
        s  += __shfl_down_sync(0xffffffffu, s, o);
        s8 += __shfl_down_sync(0xffffffffu, s8, o);
    }
    if (lane == 0) {
        if (w < NROW) { g_x2[r] = s; g_x28[r] = s8; }
        else          { g_y2[r] = s; g_y28[r] = s8; }
    }
}

// ---------------- scan: screen on first 8 dims, exact recheck on flagged pairs ----------------
__device__ void recheck(int p, const float* __restrict__ A, const float* __restrict__ B,
                        int i, int j, const float* a2, const float* b2) {
    const float4* ar = reinterpret_cast<const float4*>(A + (size_t)i * D);
    const float4* br = reinterpret_cast<const float4*>(B + (size_t)j * D);
    float dot = 0.f;
#pragma unroll 8
    for (int k = 0; k < 32; k++) {
        float4 x = ar[k], y = br[k];
        dot += x.x * y.x + x.y * y.y + x.z * y.z + x.w * y.w;
    }
    float c = fmaxf(a2[i] + b2[j] - 2.f * dot, 0.f);
    float sc = fmaxf(-c / 0.01f, -50.f);            // upper clip at 0 inactive since c>=0
    float K = fmaxf(expf(sc), EPS_STAB);
    float dk = K - EPS_STAB;
    if (dk > 0.f) {
        float dkc = dk * c;
        if (i == j) {
            g_dk_diag[p][i]  = dk;
            g_dkc_diag[p][i] = dkc;
        } else {
            int idx = atomicAdd(&g_sp_cnt[p], 1);
            if (idx < SP_CAP) {
                g_sp_i[p][idx] = i;  g_sp_j[p][idx] = j;
                g_sp_dk[p][idx] = dk; g_sp_dkc[p][idx] = dkc;
            }
        }
    }
}

__global__ void __launch_bounds__(256) k_scan(const float* __restrict__ X, const float* __restrict__ Y) {
    int p = blockIdx.z;
    const float* A   = (p == 2) ? Y : X;
    const float* B   = (p == 0) ? Y : ((p == 1) ? X : Y);
    const float* a2  = (p == 2) ? g_y2 : g_x2;
    const float* b2  = (p == 0) ? g_y2 : ((p == 1) ? g_x2 : g_y2);
    const float* a28 = (p == 2) ? g_y28 : g_x28;
    const float* b28 = (p == 0) ? g_y28 : ((p == 1) ? g_x28 : g_y28);

    __shared__ float As[8][132];
    __shared__ float Bs[8][132];
    int i0 = blockIdx.y * 128, j0 = blockIdx.x * 128;

    {   // each of 256 threads loads one float4 from A and one from B (8 coords per row)
        int row = threadIdx.x >> 1;
        int h = (threadIdx.x & 1) * 4;
        float4 xa = *reinterpret_cast<const float4*>(A + (size_t)(i0 + row) * D + h);
        As[h + 0][row] = xa.x; As[h + 1][row] = xa.y; As[h + 2][row] = xa.z; As[h + 3][row] = xa.w;
        float4 xb = *reinterpret_cast<const float4*>(B + (size_t)(j0 + row) * D + h);
        Bs[h + 0][row] = xb.x; Bs[h + 1][row] = xb.y; Bs[h + 2][row] = xb.z; Bs[h + 3][row] = xb.w;
    }
    __syncthreads();

    int tx = threadIdx.x & 15, ty = threadIdx.x >> 4;
    int ib = ty * 8, jb = tx * 8;
    float acc[8][8];
#pragma unroll
    for (int r = 0; r < 8; r++)
#pragma unroll
        for (int s = 0; s < 8; s++) acc[r][s] = 0.f;

#pragma unroll
    for (int k = 0; k < 8; k++) {
        float xs[8], ys[8];
#pragma unroll
        for (int r = 0; r < 8; r++) xs[r] = As[k][ib + r];
#pragma unroll
        for (int s = 0; s < 8; s++) ys[s] = Bs[k][jb + s];
#pragma unroll
        for (int r = 0; r < 8; r++)
#pragma unroll
            for (int s = 0; s < 8; s++) acc[r][s] = fmaf(xs[r], ys[s], acc[r][s]);
    }

#pragma unroll
    for (int r = 0; r < 8; r++) {
        int i = i0 + ib + r;
        float ai = a28[i];
#pragma unroll
        for (int s = 0; s < 8; s++) {
            int j = j0 + jb + s;
            float c8 = ai + b28[j] - 2.f * acc[r][s];   // lower bound of true C_ij
            if (c8 < 0.5f) recheck(p, A, B, i, j, a2, b2);
        }
    }
}

// ---------------- block-wide sum (works for 1024 and 128 threads) ----------------
__device__ __forceinline__ float blockSum(float x, float* red) {
    int lane = threadIdx.x & 31, w = threadIdx.x >> 5;
#pragma unroll
    for (int o = 16; o; o >>= 1) x += __shfl_down_sync(0xffffffffu, x, o);
    if (lane == 0) red[w] = x;
    __syncthreads();
    int nw = blockDim.x >> 5;
    if (w == 0) {
        float y = (lane < nw) ? red[lane] : 0.f;
#pragma unroll
        for (int o = 16; o; o >>= 1) y += __shfl_down_sync(0xffffffffu, y, o);
        if (lane == 0) red[0] = y;
    }
    __syncthreads();
    float r = red[0];
    __syncthreads();
    return r;
}

// ---------------- Sinkhorn iterations, O(n) per iter; one block per pairing ----------------
__global__ void __launch_bounds__(1024, 1) k_iter() {
    int p = blockIdx.x;
    int t = threadIdx.x;                       // 1024 threads, 8 elems each
    const float* r2 = (p == 2) ? g_y2 : g_x2;  // row norms
    const float* c2 = (p == 0) ? g_y2 : ((p == 1) ? g_x2 : g_y2); // col norms

    float u[8], v[8], dk[8], dkc[8];
#pragma unroll
    for (int k = 0; k < 8; k++) {
        int i = t + k * 1024;
        v[k] = 1.f; u[k] = 1.f;
        dk[k]  = g_dk_diag[p][i];
        dkc[k] = g_dkc_diag[p][i];
    }
    int off = min(g_sp_cnt[p], SP_CAP);
    __shared__ float red[33];
    const float a = 1.f / NROW, b = 1.f / NROW, s = EPS_STAB;

    for (int it = 0; it < 100; it++) {
        // --- Kv, u update ---
        float lv = ((v[0] + v[1]) + (v[2] + v[3])) + ((v[4] + v[5]) + (v[6] + v[7]));
        float sv = blockSum(lv, red);
        if (off) {
#pragma unroll
            for (int k = 0; k < 8; k++) { g_v[p][t + k * 1024] = v[k]; g_acc[p][t + k * 1024] = 0.f; }
            __syncthreads();
            for (int e = t; e < off; e += 1024)
                atomicAdd(&g_acc[p][g_sp_i[p][e]], g_sp_dk[p][e] * g_v[p][g_sp_j[p][e]]);
            __syncthreads();
        }
#pragma unroll
        for (int k = 0; k < 8; k++) {
            float kv = fmaf(dk[k], v[k], s * sv);
            if (off) kv += g_acc[p][t + k * 1024];
            u[k] = a / fmaxf(kv, s);
        }
        // --- K^T u, v update ---
        float lu = ((u[0] + u[1]) + (u[2] + u[3])) + ((u[4] + u[5]) + (u[6] + u[7]));
        float su = blockSum(lu, red);
        if (off) {
#pragma unroll
            for (int k = 0; k < 8; k++) { g_u[p][t + k * 1024] = u[k]; g_acc[p][t + k * 1024] = 0.f; }
            __syncthreads();
            for (int e = t; e < off; e += 1024)
                atomicAdd(&g_acc[p][g_sp_j[p][e]], g_sp_dk[p][e] * g_u[p][g_sp_i[p][e]]);
            __syncthreads();
        }
#pragma unroll
        for (int k = 0; k < 8; k++) {
            float ku = fmaf(dk[k], u[k], s * su);
            if (off) ku += g_acc[p][t + k * 1024];
            v[k] = b / fmaxf(ku, s);
        }
    }

    // final scalar reductions + publish u,v
    float lsu = 0.f, lsv = 0.f, lux2 = 0.f, lvy2 = 0.f, ldc = 0.f;
#pragma unroll
    for (int k = 0; k < 8; k++) {
        int i = t + k * 1024;
        lsu += u[k]; lsv += v[k];
        lux2 = fmaf(u[k], r2[i], lux2);
        lvy2 = fmaf(v[k], c2[i], lvy2);
        ldc  = fmaf(dkc[k], u[k] * v[k], ldc);
        g_u[p][i] = u[k]; g_v[p][i] = v[k];
    }
    float rsu  = blockSum(lsu, red);
    float rsv  = blockSum(lsv, red);
    float rux2 = blockSum(lux2, red);
    float rvy2 = blockSum(lvy2, red);
    float rdc  = blockSum(ldc, red);
    if (t == 0) {
        g_scal[p][0] = rsu; g_scal[p][1] = rsv;
        g_scal[p][2] = rux2; g_scal[p][3] = rvy2; g_scal[p][4] = rdc;
    }
}

// ---------------- weighted column sums: X^T u and Y^T v per pairing ----------------
__global__ void k_colsum(const float* __restrict__ X, const float* __restrict__ Y) {
    int task = blockIdx.y;           // 0..5
    int p = task >> 1, side = task & 1;
    const float* M; const float* w;
    if (side == 0) { M = (p == 2) ? Y : X; w = g_u[p]; }
    else           { M = (p == 0) ? Y : ((p == 1) ? X : Y); w = g_v[p]; }
    int col = threadIdx.x;           // 128
    int r0 = blockIdx.x * (NROW / 16);
    float a0 = 0.f, a1 = 0.f, a2 = 0.f, a3 = 0.f;
    for (int r = r0; r < r0 + NROW / 16; r += 4) {
        a0 = fmaf(w[r + 0], M[(size_t)(r + 0) * D + col], a0);
        a1 = fmaf(w[r + 1], M[(size_t)(r + 1) * D + col], a1);
        a2 = fmaf(w[r + 2], M[(size_t)(r + 2) * D + col], a2);
        a3 = fmaf(w[r + 3], M[(size_t)(r + 3) * D + col], a3);
    }
    atomicAdd(&g_PQ[task][col], (a0 + a1) + (a2 + a3));
}

// ---------------- assemble costs and divergence ----------------
__global__ void k_final(float* __restrict__ out) {
    __shared__ float red[33];
    __shared__ float costs[3];
    int t = threadIdx.x;  // 128
    for (int p = 0; p < 3; p++) {
        float x = g_PQ[2 * p][t] * g_PQ[2 * p + 1][t];
        float pq = blockSum(x, red);
        float oc = 0.f;
        int off = min(g_sp_cnt[p], SP_CAP);
        for (int e = t; e < off; e += 128)
            oc += g_sp_dkc[p][e] * g_u[p][g_sp_i[p][e]] * g_v[p][g_sp_j[p][e]];
        oc = blockSum(oc, red);
        if (t == 0) {
            float su = g_scal[p][0], sv = g_scal[p][1];
            float ux2 = g_scal[p][2], vy2 = g_scal[p][3], dc = g_scal[p][4];
            float cost = EPS_STAB * (ux2 * sv + su * vy2 - 2.f * pq) + dc + oc;
            costs[p] = fmaxf(cost, 0.f);
        }
        __syncthreads();
    }
    if (t == 0) {
        float div = costs[0] - 0.5f * (costs[1] + costs[2]);
        out[0] = fminf(fmaxf(div, 0.f), 10000.f);
    }
}

// ---------------- launch ----------------
extern "C" void kernel_launch(void* const* d_in, const int* in_sizes, int n_in,
                              void* d_out, int out_size) {
    const float* X = (const float*)d_in[0];
    const float* Y = (const float*)d_in[1];
    float* out = (float*)d_out;
    (void)in_sizes; (void)n_in; (void)out_size;

    k_init<<<64, 256>>>();
    k_norms<<<(2 * NROW) / 8, 256>>>(X, Y);                  // one warp per row
    k_scan<<<dim3(NROW / 128, NROW / 128, 3), 256>>>(X, Y);  // 128x128 pair tiles
    k_iter<<<3, 1024>>>();                                   // one block per pairing
    k_colsum<<<dim3(16, 6), 128>>>(X, Y);
    k_final<<<1, 128>>>(out);
}

// round 3
// speedup vs baseline: 1.0688x; 1.0688x over previous
#include <cuda_runtime.h>

#define NROW 8192
#define D 128
#define NPAIR 3
#define SP_CAP 32768
#define EPS_STAB 1e-8f

// ---------------- device globals (scratch; no allocs allowed) ----------------
__device__ float g_x2[NROW], g_y2[NROW], g_x28[NROW], g_y28[NROW];
__device__ float g_dk_diag[NPAIR][NROW];
__device__ float g_dkc_diag[NPAIR][NROW];
__device__ int   g_sp_cnt[NPAIR];
__device__ int   g_sp_i[NPAIR][SP_CAP];
__device__ int   g_sp_j[NPAIR][SP_CAP];
__device__ float g_sp_dk[NPAIR][SP_CAP];
__device__ float g_sp_dkc[NPAIR][SP_CAP];
__device__ float g_u[NPAIR][NROW], g_v[NPAIR][NROW], g_acc[NPAIR][NROW];
__device__ float g_scal[NPAIR][5];   // su, sv, u.x2, v.y2, diag cost
__device__ float g_PQ[6][D];         // X^T u / Y^T v per pairing

// ---------------- init: zero scratch ----------------
__global__ void k_init() {
    int t = blockIdx.x * blockDim.x + threadIdx.x;
    int tot = blockDim.x * gridDim.x;
    float* dk  = &g_dk_diag[0][0];
    float* dkc = &g_dkc_diag[0][0];
    for (int i = t; i < NPAIR * NROW; i += tot) { dk[i] = 0.f; dkc[i] = 0.f; }
    float* pq = &g_PQ[0][0];
    for (int i = t; i < 6 * D; i += tot) pq[i] = 0.f;
    if (t < NPAIR) g_sp_cnt[t] = 0;
}

// ---------------- row norms (full 128 and first-8) ----------------
__global__ void k_norms(const float* __restrict__ X, const float* __restrict__ Y) {
    int w = (blockIdx.x * blockDim.x + threadIdx.x) >> 5;
    int lane = threadIdx.x & 31;
    if (w >= 2 * NROW) return;
    const float* M = (w < NROW) ? X : Y;
    int r = (w < NROW) ? w : (w - NROW);
    float4 a = reinterpret_cast<const float4*>(M + (size_t)r * D)[lane];
    float s = a.x * a.x + a.y * a.y + a.z * a.z + a.w * a.w;
    float s8 = (lane < 2) ? s : 0.f;
#pragma unroll
    for (int o = 16; o; o >>= 1) {
        s  += __shfl_down_sync(0xffffffffu, s, o);
        s8 += __shfl_down_sync(0xffffffffu, s8, o);
    }
    if (lane == 0) {
        if (w < NROW) { g_x2[r] = s; g_x28[r] = s8; }
        else          { g_y2[r] = s; g_y28[r] = s8; }
    }
}

// ---------------- exact recheck on flagged pairs (rare; keep out of hot loop) ----
__device__ __noinline__ void recheck(int p, const float* __restrict__ A, const float* __restrict__ B,
                                     int i, int j, const float* a2, const float* b2) {
    const float4* ar = reinterpret_cast<const float4*>(A + (size_t)i * D);
    const float4* br = reinterpret_cast<const float4*>(B + (size_t)j * D);
    float dot = 0.f;
#pragma unroll 8
    for (int k = 0; k < 32; k++) {
        float4 x = ar[k], y = br[k];
        dot += x.x * y.x + x.y * y.y + x.z * y.z + x.w * y.w;
    }
    float c = fmaxf(a2[i] + b2[j] - 2.f * dot, 0.f);
    float sc = fmaxf(-c / 0.01f, -50.f);            // upper clip at 0 inactive since c>=0
    float K = fmaxf(expf(sc), EPS_STAB);
    float dk = K - EPS_STAB;
    if (dk > 0.f) {
        float dkc = dk * c;
        if (i == j) {
            g_dk_diag[p][i]  = dk;
            g_dkc_diag[p][i] = dkc;
        } else {
            int idx = atomicAdd(&g_sp_cnt[p], 1);
            if (idx < SP_CAP) {
                g_sp_i[p][idx] = i;  g_sp_j[p][idx] = j;
                g_sp_dk[p][idx] = dk; g_sp_dkc[p][idx] = dkc;
            }
        }
    }
}

// ---------------- scan: screen on first 8 dims ----------------
__global__ void __launch_bounds__(256) k_scan(const float* __restrict__ X, const float* __restrict__ Y) {
    int p = blockIdx.z;
    const float* A   = (p == 2) ? Y : X;
    const float* B   = (p == 0) ? Y : ((p == 1) ? X : Y);
    const float* a2  = (p == 2) ? g_y2 : g_x2;
    const float* b2  = (p == 0) ? g_y2 : ((p == 1) ? g_x2 : g_y2);
    const float* a28 = (p == 2) ? g_y28 : g_x28;
    const float* b28 = (p == 0) ? g_y28 : ((p == 1) ? g_x28 : g_y28);

    __shared__ float As[8][132];
    __shared__ float Bs[8][132];
    __shared__ float sa28[128];
    __shared__ float sb28[128];
    int i0 = blockIdx.y * 128, j0 = blockIdx.x * 128;

    {   // each of 256 threads loads one float4 from A and one from B (8 coords per row)
        int row = threadIdx.x >> 1;
        int h = (threadIdx.x & 1) * 4;
        float4 xa = *reinterpret_cast<const float4*>(A + (size_t)(i0 + row) * D + h);
        As[h + 0][row] = xa.x; As[h + 1][row] = xa.y; As[h + 2][row] = xa.z; As[h + 3][row] = xa.w;
        float4 xb = *reinterpret_cast<const float4*>(B + (size_t)(j0 + row) * D + h);
        Bs[h + 0][row] = xb.x; Bs[h + 1][row] = xb.y; Bs[h + 2][row] = xb.z; Bs[h + 3][row] = xb.w;
        // stage screen norms once per block (kills the per-pair global loads)
        if (threadIdx.x < 128) sa28[threadIdx.x] = a28[i0 + threadIdx.x];
        else                   sb28[threadIdx.x - 128] = b28[j0 + threadIdx.x - 128];
    }
    __syncthreads();

    int tx = threadIdx.x & 15, ty = threadIdx.x >> 4;
    int ib = ty * 8, jb = tx * 8;
    float acc[8][8];
#pragma unroll
    for (int r = 0; r < 8; r++)
#pragma unroll
        for (int s = 0; s < 8; s++) acc[r][s] = 0.f;

#pragma unroll
    for (int k = 0; k < 8; k++) {
        float4 x0 = *reinterpret_cast<const float4*>(&As[k][ib]);
        float4 x1 = *reinterpret_cast<const float4*>(&As[k][ib + 4]);
        float4 y0 = *reinterpret_cast<const float4*>(&Bs[k][jb]);
        float4 y1 = *reinterpret_cast<const float4*>(&Bs[k][jb + 4]);
        float xs[8] = {x0.x, x0.y, x0.z, x0.w, x1.x, x1.y, x1.z, x1.w};
        float ys[8] = {y0.x, y0.y, y0.z, y0.w, y1.x, y1.y, y1.z, y1.w};
#pragma unroll
        for (int r = 0; r < 8; r++)
#pragma unroll
            for (int s = 0; s < 8; s++) acc[r][s] = fmaf(xs[r], ys[s], acc[r][s]);
    }

    float ai[8], bj[8];
#pragma unroll
    for (int r = 0; r < 8; r++) ai[r] = sa28[ib + r];
#pragma unroll
    for (int s = 0; s < 8; s++) bj[s] = sb28[jb + s];

#pragma unroll
    for (int r = 0; r < 8; r++) {
#pragma unroll
        for (int s = 0; s < 8; s++) {
            float c8 = ai[r] + bj[s] - 2.f * acc[r][s];   // lower bound of true C_ij
            if (c8 < 0.5f)
                recheck(p, A, B, i0 + ib + r, j0 + jb + s, a2, b2);
        }
    }
}

// ---------------- single-barrier block sum (butterfly, double-buffered) ----------------
__device__ __forceinline__ float blockSumFast(float x, float* red, int call) {
    int lane = threadIdx.x & 31, w = threadIdx.x >> 5;
    int nw = blockDim.x >> 5;
#pragma unroll
    for (int o = 16; o; o >>= 1) x += __shfl_xor_sync(0xffffffffu, x, o);
    float* buf = red + (call & 1) * 32;
    if (lane == 0) buf[w] = x;
    __syncthreads();
    float y = (lane < nw) ? buf[lane] : 0.f;
#pragma unroll
    for (int o = 16; o; o >>= 1) y += __shfl_xor_sync(0xffffffffu, y, o);
    return y;   // all threads hold the total
}

// ---------------- Sinkhorn iterations, O(n) per iter; one block per pairing ----------------
__global__ void __launch_bounds__(1024, 1) k_iter() {
    int p = blockIdx.x;
    int t = threadIdx.x;                       // 1024 threads, 8 elems each
    const float* r2 = (p == 2) ? g_y2 : g_x2;  // row norms
    const float* c2 = (p == 0) ? g_y2 : ((p == 1) ? g_x2 : g_y2); // col norms

    float u[8], v[8], dk[8], dkc[8];
#pragma unroll
    for (int k = 0; k < 8; k++) {
        int i = t + k * 1024;
        v[k] = 1.f; u[k] = 1.f;
        dk[k]  = g_dk_diag[p][i];
        dkc[k] = g_dkc_diag[p][i];
    }
    int off = min(g_sp_cnt[p], SP_CAP);
    __shared__ float red[64];
    const float a = 1.f / NROW, b = 1.f / NROW, s = EPS_STAB;
    int call = 0;

    for (int it = 0; it < 100; it++) {
        // --- Kv, u update ---
        float lv = ((v[0] + v[1]) + (v[2] + v[3])) + ((v[4] + v[5]) + (v[6] + v[7]));
        float sv = blockSumFast(lv, red, call++);
        if (off) {
#pragma unroll
            for (int k = 0; k < 8; k++) { g_v[p][t + k * 1024] = v[k]; g_acc[p][t + k * 1024] = 0.f; }
            __syncthreads();
            for (int e = t; e < off; e += 1024)
                atomicAdd(&g_acc[p][g_sp_i[p][e]], g_sp_dk[p][e] * g_v[p][g_sp_j[p][e]]);
            __syncthreads();
        }
#pragma unroll
        for (int k = 0; k < 8; k++) {
            float kv = fmaf(dk[k], v[k], s * sv);
            if (off) kv += g_acc[p][t + k * 1024];
            u[k] = a / fmaxf(kv, s);
        }
        // --- K^T u, v update ---
        float lu = ((u[0] + u[1]) + (u[2] + u[3])) + ((u[4] + u[5]) + (u[6] + u[7]));
        float su = blockSumFast(lu, red, call++);
        if (off) {
#pragma unroll
            for (int k = 0; k < 8; k++) { g_u[p][t + k * 1024] = u[k]; g_acc[p][t + k * 1024] = 0.f; }
            __syncthreads();
            for (int e = t; e < off; e += 1024)
                atomicAdd(&g_acc[p][g_sp_j[p][e]], g_sp_dk[p][e] * g_u[p][g_sp_i[p][e]]);
            __syncthreads();
        }
#pragma unroll
        for (int k = 0; k < 8; k++) {
            float ku = fmaf(dk[k], u[k], s * su);
            if (off) ku += g_acc[p][t + k * 1024];
            v[k] = b / fmaxf(ku, s);
        }
    }

    // final scalar reductions + publish u,v
    float lsu = 0.f, lsv = 0.f, lux2 = 0.f, lvy2 = 0.f, ldc = 0.f;
#pragma unroll
    for (int k = 0; k < 8; k++) {
        int i = t + k * 1024;
        lsu += u[k]; lsv += v[k];
        lux2 = fmaf(u[k], r2[i], lux2);
        lvy2 = fmaf(v[k], c2[i], lvy2);
        ldc  = fmaf(dkc[k], u[k] * v[k], ldc);
        g_u[p][i] = u[k]; g_v[p][i] = v[k];
    }
    float rsu  = blockSumFast(lsu,  red, call++);
    float rsv  = blockSumFast(lsv,  red, call++);
    float rux2 = blockSumFast(lux2, red, call++);
    float rvy2 = blockSumFast(lvy2, red, call++);
    float rdc  = blockSumFast(ldc,  red, call++);
    if (t == 0) {
        g_scal[p][0] = rsu; g_scal[p][1] = rsv;
        g_scal[p][2] = rux2; g_scal[p][3] = rvy2; g_scal[p][4] = rdc;
    }
}

// ---------------- weighted column sums: X^T u and Y^T v per pairing ----------------
__global__ void k_colsum(const float* __restrict__ X, const float* __restrict__ Y) {
    int task = blockIdx.y;           // 0..5
    int p = task >> 1, side = task & 1;
    const float* M; const float* w;
    if (side == 0) { M = (p == 2) ? Y : X; w = g_u[p]; }
    else           { M = (p == 0) ? Y : ((p == 1) ? X : Y); w = g_v[p]; }
    int col = threadIdx.x;           // 128
    int r0 = blockIdx.x * (NROW / 16);
    float a0 = 0.f, a1 = 0.f, a2 = 0.f, a3 = 0.f;
    for (int r = r0; r < r0 + NROW / 16; r += 4) {
        a0 = fmaf(w[r + 0], M[(size_t)(r + 0) * D + col], a0);
        a1 = fmaf(w[r + 1], M[(size_t)(r + 1) * D + col], a1);
        a2 = fmaf(w[r + 2], M[(size_t)(r + 2) * D + col], a2);
        a3 = fmaf(w[r + 3], M[(size_t)(r + 3) * D + col], a3);
    }
    atomicAdd(&g_PQ[task][col], (a0 + a1) + (a2 + a3));
}

// ---------------- assemble costs and divergence ----------------
__global__ void k_final(float* __restrict__ out) {
    __shared__ float red[64];
    __shared__ float costs[3];
    int t = threadIdx.x;  // 128
    int call = 0;
    for (int p = 0; p < 3; p++) {
        float x = g_PQ[2 * p][t] * g_PQ[2 * p + 1][t];
        float pq = blockSumFast(x, red, call++);
        float oc = 0.f;
        int off = min(g_sp_cnt[p], SP_CAP);
        for (int e = t; e < off; e += 128)
            oc += g_sp_dkc[p][e] * g_u[p][g_sp_i[p][e]] * g_v[p][g_sp_j[p][e]];
        oc = blockSumFast(oc, red, call++);
        if (t == 0) {
            float su = g_scal[p][0], sv = g_scal[p][1];
            float ux2 = g_scal[p][2], vy2 = g_scal[p][3], dc = g_scal[p][4];
            float cost = EPS_STAB * (ux2 * sv + su * vy2 - 2.f * pq) + dc + oc;
            costs[p] = fmaxf(cost, 0.f);
        }
        __syncthreads();
    }
    if (t == 0) {
        float div = costs[0] - 0.5f * (costs[1] + costs[2]);
        out[0] = fminf(fmaxf(div, 0.f), 10000.f);
    }
}

// ---------------- launch ----------------
extern "C" void kernel_launch(void* const* d_in, const int* in_sizes, int n_in,
                              void* d_out, int out_size) {
    const float* X = (const float*)d_in[0];
    const float* Y = (const float*)d_in[1];
    float* out = (float*)d_out;
    (void)in_sizes; (void)n_in; (void)out_size;

    k_init<<<64, 256>>>();
    k_norms<<<(2 * NROW) / 8, 256>>>(X, Y);                  // one warp per row
    k_scan<<<dim3(NROW / 128, NROW / 128, 3), 256>>>(X, Y);  // 128x128 pair tiles
    k_iter<<<3, 1024>>>();                                   // one block per pairing
    k_colsum<<<dim3(16, 6), 128>>>(X, Y);
    k_final<<<1, 128>>>(out);
}

// round 4
// speedup vs baseline: 1.6952x; 1.5861x over previous
#include <cuda_runtime.h>

#define NROW 8192
#define D 128
#define NPAIR 3
#define SP_CAP 32768
#define EPS_STAB 1e-8f
#define TPB_TILES 8   // consecutive j-tiles handled per block (same i-tile)

typedef unsigned long long u64;

// ---------------- packed f32x2 helpers (sm_103a) ----------------
__device__ __forceinline__ u64 pack2(float lo, float hi) {
    u64 r; asm("mov.b64 %0, {%1, %2};" : "=l"(r) : "f"(lo), "f"(hi)); return r;
}
__device__ __forceinline__ void unpack2(u64 v, float& lo, float& hi) {
    asm("mov.b64 {%0, %1}, %2;" : "=f"(lo), "=f"(hi) : "l"(v));
}
__device__ __forceinline__ u64 addx2(u64 a, u64 b) {
    u64 r; asm("add.rn.f32x2 %0, %1, %2;" : "=l"(r) : "l"(a), "l"(b)); return r;
}
__device__ __forceinline__ void ffma2(u64& d, u64 a, u64 b) {
    asm("fma.rn.f32x2 %0, %1, %2, %3;" : "=l"(d) : "l"(a), "l"(b), "l"(d));
}
__device__ __forceinline__ u64 fma2r(u64 a, u64 b, u64 c) {
    u64 r; asm("fma.rn.f32x2 %0, %1, %2, %3;" : "=l"(r) : "l"(a), "l"(b), "l"(c)); return r;
}

// ---------------- device globals (scratch; no allocs allowed) ----------------
__device__ float g_x2[NROW], g_y2[NROW], g_x28[NROW], g_y28[NROW];
__device__ float g_dk_diag[NPAIR][NROW];
__device__ float g_dkc_diag[NPAIR][NROW];
__device__ int   g_sp_cnt[NPAIR];
__device__ int   g_sp_i[NPAIR][SP_CAP];
__device__ int   g_sp_j[NPAIR][SP_CAP];
__device__ float g_sp_dk[NPAIR][SP_CAP];
__device__ float g_sp_dkc[NPAIR][SP_CAP];
__device__ float g_u[NPAIR][NROW], g_v[NPAIR][NROW], g_acc[NPAIR][NROW];
__device__ float g_scal[NPAIR][5];   // su, sv, u.x2, v.y2, diag cost
__device__ float g_PQ[6][D];         // X^T u / Y^T v per pairing

// ---------------- init: zero scratch ----------------
__global__ void k_init() {
    int t = blockIdx.x * blockDim.x + threadIdx.x;
    int tot = blockDim.x * gridDim.x;
    float* dk  = &g_dk_diag[0][0];
    float* dkc = &g_dkc_diag[0][0];
    for (int i = t; i < NPAIR * NROW; i += tot) { dk[i] = 0.f; dkc[i] = 0.f; }
    float* pq = &g_PQ[0][0];
    for (int i = t; i < 6 * D; i += tot) pq[i] = 0.f;
    if (t < NPAIR) g_sp_cnt[t] = 0;
}

// ---------------- row norms (full 128 and first-8) ----------------
__global__ void k_norms(const float* __restrict__ X, const float* __restrict__ Y) {
    int w = (blockIdx.x * blockDim.x + threadIdx.x) >> 5;
    int lane = threadIdx.x & 31;
    if (w >= 2 * NROW) return;
    const float* M = (w < NROW) ? X : Y;
    int r = (w < NROW) ? w : (w - NROW);
    float4 a = reinterpret_cast<const float4*>(M + (size_t)r * D)[lane];
    float s = a.x * a.x + a.y * a.y + a.z * a.z + a.w * a.w;
    float s8 = (lane < 2) ? s : 0.f;
#pragma unroll
    for (int o = 16; o; o >>= 1) {
        s  += __shfl_down_sync(0xffffffffu, s, o);
        s8 += __shfl_down_sync(0xffffffffu, s8, o);
    }
    if (lane == 0) {
        if (w < NROW) { g_x2[r] = s; g_x28[r] = s8; }
        else          { g_y2[r] = s; g_y28[r] = s8; }
    }
}

// ---------------- exact recheck on flagged pairs (rare; cold) ----
__device__ __noinline__ void recheck(int p, const float* __restrict__ A, const float* __restrict__ B,
                                     int i, int j, const float* a2, const float* b2) {
    const float4* ar = reinterpret_cast<const float4*>(A + (size_t)i * D);
    const float4* br = reinterpret_cast<const float4*>(B + (size_t)j * D);
    float dot = 0.f;
#pragma unroll 8
    for (int k = 0; k < 32; k++) {
        float4 x = ar[k], y = br[k];
        dot += x.x * y.x + x.y * y.y + x.z * y.z + x.w * y.w;
    }
    float c = fmaxf(a2[i] + b2[j] - 2.f * dot, 0.f);
    float sc = fmaxf(-c / 0.01f, -50.f);            // upper clip at 0 inactive since c>=0
    float K = fmaxf(expf(sc), EPS_STAB);
    float dk = K - EPS_STAB;
    if (dk > 0.f) {
        float dkc = dk * c;
        if (i == j) {
            g_dk_diag[p][i]  = dk;
            g_dkc_diag[p][i] = dkc;
        } else {
            int idx = atomicAdd(&g_sp_cnt[p], 1);
            if (idx < SP_CAP) {
                g_sp_i[p][idx] = i;  g_sp_j[p][idx] = j;
                g_sp_dk[p][idx] = dk; g_sp_dkc[p][idx] = dkc;
            }
        }
    }
}

// ---------------- scan: 8-dim screen, f32x2 GEMM, branchless epilogue ----------------
__global__ void __launch_bounds__(256, 2) k_scan(const float* __restrict__ X, const float* __restrict__ Y) {
    int tile0 = blockIdx.x * TPB_TILES;
    int p   = tile0 >> 12;        // 4096 tiles per pairing (64 x 64)
    int rem = tile0 & 4095;
    int ti  = rem >> 6;           // i-tile, constant within block
    int tj0 = rem & 63;           // first j-tile (multiple of TPB_TILES)

    const float* A   = (p == 2) ? Y : X;
    const float* B   = (p == 0) ? Y : ((p == 1) ? X : Y);
    const float* a2  = (p == 2) ? g_y2 : g_x2;
    const float* b2  = (p == 0) ? g_y2 : ((p == 1) ? g_x2 : g_y2);
    const float* a28 = (p == 2) ? g_y28 : g_x28;
    const float* b28 = (p == 0) ? g_y28 : ((p == 1) ? g_x28 : g_y28);

    __shared__ __align__(16) float As[8][132];
    __shared__ __align__(16) float Bs[8][132];
    __shared__ __align__(16) float sa28[128];
    __shared__ __align__(16) float sb28[128];

    int i0 = ti * 128;
    {   // load A tile once (8 coords per row) + screen norms
        int row = threadIdx.x >> 1;
        int h = (threadIdx.x & 1) * 4;
        float4 xa = *reinterpret_cast<const float4*>(A + (size_t)(i0 + row) * D + h);
        As[h + 0][row] = xa.x; As[h + 1][row] = xa.y; As[h + 2][row] = xa.z; As[h + 3][row] = xa.w;
        if (threadIdx.x < 128) sa28[threadIdx.x] = a28[i0 + threadIdx.x];
    }

    int tx = threadIdx.x & 15, ty = threadIdx.x >> 4;
    int ib = ty * 8, jb = tx * 8;
    const u64 NEG2 = pack2(-2.f, -2.f);

    for (int tt = 0; tt < TPB_TILES; tt++) {
        int j0 = (tj0 + tt) * 128;
        {   // load B tile + screen norms
            int row = threadIdx.x >> 1;
            int h = (threadIdx.x & 1) * 4;
            float4 xb = *reinterpret_cast<const float4*>(B + (size_t)(j0 + row) * D + h);
            Bs[h + 0][row] = xb.x; Bs[h + 1][row] = xb.y; Bs[h + 2][row] = xb.z; Bs[h + 3][row] = xb.w;
            if (threadIdx.x >= 128) sb28[threadIdx.x - 128] = b28[j0 + threadIdx.x - 128];
        }
        __syncthreads();

        u64 acc[8][4];
#pragma unroll
        for (int r = 0; r < 8; r++)
#pragma unroll
            for (int s2 = 0; s2 < 4; s2++) acc[r][s2] = 0ull;   // (0.f, 0.f)

#pragma unroll
        for (int k = 0; k < 8; k++) {
            float4 x0 = *reinterpret_cast<const float4*>(&As[k][ib]);
            float4 x1 = *reinterpret_cast<const float4*>(&As[k][ib + 4]);
            ulonglong2 yA = *reinterpret_cast<const ulonglong2*>(&Bs[k][jb]);
            ulonglong2 yB = *reinterpret_cast<const ulonglong2*>(&Bs[k][jb + 4]);
            u64 yv[4] = {yA.x, yA.y, yB.x, yB.y};
            u64 xd[8] = {pack2(x0.x, x0.x), pack2(x0.y, x0.y), pack2(x0.z, x0.z), pack2(x0.w, x0.w),
                         pack2(x1.x, x1.x), pack2(x1.y, x1.y), pack2(x1.z, x1.z), pack2(x1.w, x1.w)};
#pragma unroll
            for (int r = 0; r < 8; r++)
#pragma unroll
                for (int s2 = 0; s2 < 4; s2++) ffma2(acc[r][s2], xd[r], yv[s2]);
        }

        // branchless screen: c8 = (-2)*dot8 + (ai + bj)  (lower bound of C_ij)
        ulonglong2 bA = *reinterpret_cast<const ulonglong2*>(&sb28[jb]);
        ulonglong2 bB = *reinterpret_cast<const ulonglong2*>(&sb28[jb + 4]);
        u64 bj2[4] = {bA.x, bA.y, bB.x, bB.y};
        float mn0 = 1e30f, mn1 = 1e30f;
#pragma unroll
        for (int r = 0; r < 8; r++) {
            float ar = sa28[ib + r];
            u64 ard = pack2(ar, ar);
#pragma unroll
            for (int s2 = 0; s2 < 4; s2++) {
                u64 c2v = fma2r(acc[r][s2], NEG2, addx2(ard, bj2[s2]));
                float clo, chi; unpack2(c2v, clo, chi);
                mn0 = fminf(mn0, clo);
                mn1 = fminf(mn1, chi);
            }
        }
        if (__any_sync(0xffffffffu, fminf(mn0, mn1) < 0.5f)) {
            // cold rescan: recompute c8 per element, exact recheck on hits
            for (int r = 0; r < 8; r++) {
                float ar = sa28[ib + r];
                u64 ard = pack2(ar, ar);
                for (int s2 = 0; s2 < 4; s2++) {
                    u64 c2v = fma2r(acc[r][s2], NEG2, addx2(ard, bj2[s2]));
                    float clo, chi; unpack2(c2v, clo, chi);
                    if (clo < 0.5f) recheck(p, A, B, i0 + ib + r, j0 + jb + 2 * s2, a2, b2);
                    if (chi < 0.5f) recheck(p, A, B, i0 + ib + r, j0 + jb + 2 * s2 + 1, a2, b2);
                }
            }
        }
        __syncthreads();   // protect Bs before next tile's load
    }
}

// ---------------- single-barrier block sum (butterfly, double-buffered) ----------------
__device__ __forceinline__ float blockSumFast(float x, float* red, int call) {
    int lane = threadIdx.x & 31, w = threadIdx.x >> 5;
    int nw = blockDim.x >> 5;
#pragma unroll
    for (int o = 16; o; o >>= 1) x += __shfl_xor_sync(0xffffffffu, x, o);
    float* buf = red + (call & 1) * 32;
    if (lane == 0) buf[w] = x;
    __syncthreads();
    float y = (lane < nw) ? buf[lane] : 0.f;
#pragma unroll
    for (int o = 16; o; o >>= 1) y += __shfl_xor_sync(0xffffffffu, y, o);
    return y;   // all threads hold the total
}

// ---------------- Sinkhorn iterations, O(n) per iter; one block per pairing ----------------
__global__ void __launch_bounds__(1024, 1) k_iter() {
    int p = blockIdx.x;
    int t = threadIdx.x;                       // 1024 threads, 8 elems each
    const float* r2 = (p == 2) ? g_y2 : g_x2;  // row norms
    const float* c2 = (p == 0) ? g_y2 : ((p == 1) ? g_x2 : g_y2); // col norms

    float u[8], v[8], dk[8], dkc[8];
#pragma unroll
    for (int k = 0; k < 8; k++) {
        int i = t + k * 1024;
        v[k] = 1.f; u[k] = 1.f;
        dk[k]  = g_dk_diag[p][i];
        dkc[k] = g_dkc_diag[p][i];
    }
    int off = min(g_sp_cnt[p], SP_CAP);
    __shared__ float red[64];
    const float a = 1.f / NROW, b = 1.f / NROW, s = EPS_STAB;
    int call = 0;

    for (int it = 0; it < 100; it++) {
        // --- Kv, u update ---
        float lv = ((v[0] + v[1]) + (v[2] + v[3])) + ((v[4] + v[5]) + (v[6] + v[7]));
        float sv = blockSumFast(lv, red, call++);
        if (off) {
#pragma unroll
            for (int k = 0; k < 8; k++) { g_v[p][t + k * 1024] = v[k]; g_acc[p][t + k * 1024] = 0.f; }
            __syncthreads();
            for (int e = t; e < off; e += 1024)
                atomicAdd(&g_acc[p][g_sp_i[p][e]], g_sp_dk[p][e] * g_v[p][g_sp_j[p][e]]);
            __syncthreads();
        }
#pragma unroll
        for (int k = 0; k < 8; k++) {
            float kv = fmaf(dk[k], v[k], s * sv);
            if (off) kv += g_acc[p][t + k * 1024];
            u[k] = __fdividef(a, fmaxf(kv, s));
        }
        // --- K^T u, v update ---
        float lu = ((u[0] + u[1]) + (u[2] + u[3])) + ((u[4] + u[5]) + (u[6] + u[7]));
        float su = blockSumFast(lu, red, call++);
        if (off) {
#pragma unroll
            for (int k = 0; k < 8; k++) { g_u[p][t + k * 1024] = u[k]; g_acc[p][t + k * 1024] = 0.f; }
            __syncthreads();
            for (int e = t; e < off; e += 1024)
                atomicAdd(&g_acc[p][g_sp_j[p][e]], g_sp_dk[p][e] * g_u[p][g_sp_i[p][e]]);
            __syncthreads();
        }
#pragma unroll
        for (int k = 0; k < 8; k++) {
            float ku = fmaf(dk[k], u[k], s * su);
            if (off) ku += g_acc[p][t + k * 1024];
            v[k] = __fdividef(b, fmaxf(ku, s));
        }
    }

    // final scalar reductions + publish u,v
    float lsu = 0.f, lsv = 0.f, lux2 = 0.f, lvy2 = 0.f, ldc = 0.f;
#pragma unroll
    for (int k = 0; k < 8; k++) {
        int i = t + k * 1024;
        lsu += u[k]; lsv += v[k];
        lux2 = fmaf(u[k], r2[i], lux2);
        lvy2 = fmaf(v[k], c2[i], lvy2);
        ldc  = fmaf(dkc[k], u[k] * v[k], ldc);
        g_u[p][i] = u[k]; g_v[p][i] = v[k];
    }
    float rsu  = blockSumFast(lsu,  red, call++);
    float rsv  = blockSumFast(lsv,  red, call++);
    float rux2 = blockSumFast(lux2, red, call++);
    float rvy2 = blockSumFast(lvy2, red, call++);
    float rdc  = blockSumFast(ldc,  red, call++);
    if (t == 0) {
        g_scal[p][0] = rsu; g_scal[p][1] = rsv;
        g_scal[p][2] = rux2; g_scal[p][3] = rvy2; g_scal[p][4] = rdc;
    }
}

// ---------------- weighted column sums: X^T u and Y^T v per pairing ----------------
__global__ void k_colsum(const float* __restrict__ X, const float* __restrict__ Y) {
    int task = blockIdx.y;           // 0..5
    int p = task >> 1, side = task & 1;
    const float* M; const float* w;
    if (side == 0) { M = (p == 2) ? Y : X; w = g_u[p]; }
    else           { M = (p == 0) ? Y : ((p == 1) ? X : Y); w = g_v[p]; }
    int col = threadIdx.x;           // 128
    int r0 = blockIdx.x * (NROW / 16);
    float a0 = 0.f, a1 = 0.f, a2 = 0.f, a3 = 0.f;
    for (int r = r0; r < r0 + NROW / 16; r += 4) {
        a0 = fmaf(w[r + 0], M[(size_t)(r + 0) * D + col], a0);
        a1 = fmaf(w[r + 1], M[(size_t)(r + 1) * D + col], a1);
        a2 = fmaf(w[r + 2], M[(size_t)(r + 2) * D + col], a2);
        a3 = fmaf(w[r + 3], M[(size_t)(r + 3) * D + col], a3);
    }
    atomicAdd(&g_PQ[task][col], (a0 + a1) + (a2 + a3));
}

// ---------------- assemble costs and divergence ----------------
__global__ void k_final(float* __restrict__ out) {
    __shared__ float red[64];
    __shared__ float costs[3];
    int t = threadIdx.x;  // 128
    int call = 0;
    for (int p = 0; p < 3; p++) {
        float x = g_PQ[2 * p][t] * g_PQ[2 * p + 1][t];
        float pq = blockSumFast(x, red, call++);
        float oc = 0.f;
        int off = min(g_sp_cnt[p], SP_CAP);
        for (int e = t; e < off; e += 128)
            oc += g_sp_dkc[p][e] * g_u[p][g_sp_i[p][e]] * g_v[p][g_sp_j[p][e]];
        oc = blockSumFast(oc, red, call++);
        if (t == 0) {
            float su = g_scal[p][0], sv = g_scal[p][1];
            float ux2 = g_scal[p][2], vy2 = g_scal[p][3], dc = g_scal[p][4];
            float cost = EPS_STAB * (ux2 * sv + su * vy2 - 2.f * pq) + dc + oc;
            costs[p] = fmaxf(cost, 0.f);
        }
        __syncthreads();
    }
    if (t == 0) {
        float div = costs[0] - 0.5f * (costs[1] + costs[2]);
        out[0] = fminf(fmaxf(div, 0.f), 10000.f);
    }
}

// ---------------- launch ----------------
extern "C" void kernel_launch(void* const* d_in, const int* in_sizes, int n_in,
                              void* d_out, int out_size) {
    const float* X = (const float*)d_in[0];
    const float* Y = (const float*)d_in[1];
    float* out = (float*)d_out;
    (void)in_sizes; (void)n_in; (void)out_size;

    k_init<<<64, 256>>>();
    k_norms<<<(2 * NROW) / 8, 256>>>(X, Y);                    // one warp per row
    k_scan<<<(3 * 4096) / TPB_TILES, 256>>>(X, Y);             // 8 j-tiles per block
    k_iter<<<3, 1024>>>();                                     // one block per pairing
    k_colsum<<<dim3(16, 6), 128>>>(X, Y);
    k_final<<<1, 128>>>(out);
}

// round 5
// speedup vs baseline: 1.6957x; 1.0003x over previous
#include <cuda_runtime.h>

#define NROW 8192
#define D 128
#define NPAIR 3
#define SP_CAP 32768
#define EPS_STAB 1e-8f
#define TPB_TILES 8   // consecutive j-tiles handled per block (same i-tile)

typedef unsigned long long u64;

// ---------------- packed f32x2 helpers (sm_103a) ----------------
__device__ __forceinline__ u64 pack2(float lo, float hi) {
    u64 r; asm("mov.b64 %0, {%1, %2};" : "=l"(r) : "f"(lo), "f"(hi)); return r;
}
__device__ __forceinline__ void unpack2(u64 v, float& lo, float& hi) {
    asm("mov.b64 {%0, %1}, %2;" : "=f"(lo), "=f"(hi) : "l"(v));
}
__device__ __forceinline__ u64 addx2(u64 a, u64 b) {
    u64 r; asm("add.rn.f32x2 %0, %1, %2;" : "=l"(r) : "l"(a), "l"(b)); return r;
}
__device__ __forceinline__ void ffma2(u64& d, u64 a, u64 b) {
    asm("fma.rn.f32x2 %0, %1, %2, %3;" : "=l"(d) : "l"(a), "l"(b), "l"(d));
}
__device__ __forceinline__ u64 fma2r(u64 a, u64 b, u64 c) {
    u64 r; asm("fma.rn.f32x2 %0, %1, %2, %3;" : "=l"(r) : "l"(a), "l"(b), "l"(c)); return r;
}

// ---------------- device globals (scratch; no allocs allowed) ----------------
__device__ float g_x2[NROW], g_y2[NROW], g_x28[NROW], g_y28[NROW];
__device__ float g_dk_diag[NPAIR][NROW];
__device__ float g_dkc_diag[NPAIR][NROW];
__device__ int   g_sp_cnt[NPAIR];
__device__ int   g_sp_i[NPAIR][SP_CAP];
__device__ int   g_sp_j[NPAIR][SP_CAP];
__device__ float g_sp_dk[NPAIR][SP_CAP];
__device__ float g_sp_dkc[NPAIR][SP_CAP];
__device__ float g_u[NPAIR][NROW], g_v[NPAIR][NROW], g_acc[NPAIR][NROW];
__device__ float g_scal[NPAIR][5];   // su, sv, u.x2, v.y2, diag cost
__device__ float g_PQ[6][D];         // X^T u / Y^T v per pairing

// ---------------- init: zero scratch ----------------
__global__ void k_init() {
    int t = blockIdx.x * blockDim.x + threadIdx.x;
    int tot = blockDim.x * gridDim.x;
    float* dk  = &g_dk_diag[0][0];
    float* dkc = &g_dkc_diag[0][0];
    for (int i = t; i < NPAIR * NROW; i += tot) { dk[i] = 0.f; dkc[i] = 0.f; }
    float* pq = &g_PQ[0][0];
    for (int i = t; i < 6 * D; i += tot) pq[i] = 0.f;
    if (t < NPAIR) g_sp_cnt[t] = 0;
}

// ---------------- row norms (full 128 and first-8) ----------------
__global__ void k_norms(const float* __restrict__ X, const float* __restrict__ Y) {
    int w = (blockIdx.x * blockDim.x + threadIdx.x) >> 5;
    int lane = threadIdx.x & 31;
    if (w >= 2 * NROW) return;
    const float* M = (w < NROW) ? X : Y;
    int r = (w < NROW) ? w : (w - NROW);
    float4 a = reinterpret_cast<const float4*>(M + (size_t)r * D)[lane];
    float s = a.x * a.x + a.y * a.y + a.z * a.z + a.w * a.w;
    float s8 = (lane < 2) ? s : 0.f;
#pragma unroll
    for (int o = 16; o; o >>= 1) {
        s  += __shfl_down_sync(0xffffffffu, s, o);
        s8 += __shfl_down_sync(0xffffffffu, s8, o);
    }
    if (lane == 0) {
        if (w < NROW) { g_x2[r] = s; g_x28[r] = s8; }
        else          { g_y2[r] = s; g_y28[r] = s8; }
    }
}

// ---------------- exact recheck on flagged pairs (rare; cold) ----
__device__ __noinline__ void recheck(int p, const float* __restrict__ A, const float* __restrict__ B,
                                     int i, int j, const float* a2, const float* b2) {
    const float4* ar = reinterpret_cast<const float4*>(A + (size_t)i * D);
    const float4* br = reinterpret_cast<const float4*>(B + (size_t)j * D);
    float dot = 0.f;
#pragma unroll 8
    for (int k = 0; k < 32; k++) {
        float4 x = ar[k], y = br[k];
        dot += x.x * y.x + x.y * y.y + x.z * y.z + x.w * y.w;
    }
    float c = fmaxf(a2[i] + b2[j] - 2.f * dot, 0.f);
    float sc = fmaxf(-c / 0.01f, -50.f);            // upper clip at 0 inactive since c>=0
    float K = fmaxf(expf(sc), EPS_STAB);
    float dk = K - EPS_STAB;
    if (dk > 0.f) {
        float dkc = dk * c;
        if (i == j) {
            g_dk_diag[p][i]  = dk;
            g_dkc_diag[p][i] = dkc;
        } else {
            int idx = atomicAdd(&g_sp_cnt[p], 1);
            if (idx < SP_CAP) {
                g_sp_i[p][idx] = i;  g_sp_j[p][idx] = j;
                g_sp_dk[p][idx] = dk; g_sp_dkc[p][idx] = dkc;
            }
        }
    }
}

// ---------------- scan: 8-dim screen, f32x2 GEMM, branchless epilogue ----------------
__global__ void __launch_bounds__(256, 2) k_scan(const float* __restrict__ X, const float* __restrict__ Y) {
    int tile0 = blockIdx.x * TPB_TILES;
    int p   = tile0 >> 12;        // 4096 tiles per pairing (64 x 64)
    int rem = tile0 & 4095;
    int ti  = rem >> 6;           // i-tile, constant within block
    int tj0 = rem & 63;           // first j-tile (multiple of TPB_TILES)

    const float* A   = (p == 2) ? Y : X;
    const float* B   = (p == 0) ? Y : ((p == 1) ? X : Y);
    const float* a2  = (p == 2) ? g_y2 : g_x2;
    const float* b2  = (p == 0) ? g_y2 : ((p == 1) ? g_x2 : g_y2);
    const float* a28 = (p == 2) ? g_y28 : g_x28;
    const float* b28 = (p == 0) ? g_y28 : ((p == 1) ? g_x28 : g_y28);

    __shared__ __align__(16) float As[8][132];
    __shared__ __align__(16) float Bs[8][132];
    __shared__ __align__(16) float sa28[128];
    __shared__ __align__(16) float sb28[128];

    int i0 = ti * 128;
    {   // load A tile once (8 coords per row) + screen norms
        int row = threadIdx.x >> 1;
        int h = (threadIdx.x & 1) * 4;
        float4 xa = *reinterpret_cast<const float4*>(A + (size_t)(i0 + row) * D + h);
        As[h + 0][row] = xa.x; As[h + 1][row] = xa.y; As[h + 2][row] = xa.z; As[h + 3][row] = xa.w;
        if (threadIdx.x < 128) sa28[threadIdx.x] = a28[i0 + threadIdx.x];
    }

    int tx = threadIdx.x & 15, ty = threadIdx.x >> 4;
    int ib = ty * 8, jb = tx * 8;
    const u64 NEG2 = pack2(-2.f, -2.f);

    for (int tt = 0; tt < TPB_TILES; tt++) {
        int j0 = (tj0 + tt) * 128;
        {   // load B tile + screen norms
            int row = threadIdx.x >> 1;
            int h = (threadIdx.x & 1) * 4;
            float4 xb = *reinterpret_cast<const float4*>(B + (size_t)(j0 + row) * D + h);
            Bs[h + 0][row] = xb.x; Bs[h + 1][row] = xb.y; Bs[h + 2][row] = xb.z; Bs[h + 3][row] = xb.w;
            if (threadIdx.x >= 128) sb28[threadIdx.x - 128] = b28[j0 + threadIdx.x - 128];
        }
        __syncthreads();

        u64 acc[8][4];
#pragma unroll
        for (int r = 0; r < 8; r++)
#pragma unroll
            for (int s2 = 0; s2 < 4; s2++) acc[r][s2] = 0ull;   // (0.f, 0.f)

#pragma unroll
        for (int k = 0; k < 8; k++) {
            float4 x0 = *reinterpret_cast<const float4*>(&As[k][ib]);
            float4 x1 = *reinterpret_cast<const float4*>(&As[k][ib + 4]);
            ulonglong2 yA = *reinterpret_cast<const ulonglong2*>(&Bs[k][jb]);
            ulonglong2 yB = *reinterpret_cast<const ulonglong2*>(&Bs[k][jb + 4]);
            u64 yv[4] = {yA.x, yA.y, yB.x, yB.y};
            u64 xd[8] = {pack2(x0.x, x0.x), pack2(x0.y, x0.y), pack2(x0.z, x0.z), pack2(x0.w, x0.w),
                         pack2(x1.x, x1.x), pack2(x1.y, x1.y), pack2(x1.z, x1.z), pack2(x1.w, x1.w)};
#pragma unroll
            for (int r = 0; r < 8; r++)
#pragma unroll
                for (int s2 = 0; s2 < 4; s2++) ffma2(acc[r][s2], xd[r], yv[s2]);
        }

        // branchless screen: c8 = (-2)*dot8 + (ai + bj)  (lower bound of C_ij)
        ulonglong2 bA = *reinterpret_cast<const ulonglong2*>(&sb28[jb]);
        ulonglong2 bB = *reinterpret_cast<const ulonglong2*>(&sb28[jb + 4]);
        u64 bj2[4] = {bA.x, bA.y, bB.x, bB.y};
        float mn0 = 1e30f, mn1 = 1e30f;
#pragma unroll
        for (int r = 0; r < 8; r++) {
            float ar = sa28[ib + r];
            u64 ard = pack2(ar, ar);
#pragma unroll
            for (int s2 = 0; s2 < 4; s2++) {
                u64 c2v = fma2r(acc[r][s2], NEG2, addx2(ard, bj2[s2]));
                float clo, chi; unpack2(c2v, clo, chi);
                mn0 = fminf(mn0, clo);
                mn1 = fminf(mn1, chi);
            }
        }
        if (__any_sync(0xffffffffu, fminf(mn0, mn1) < 0.5f)) {
            // cold rescan: recompute c8 per element, exact recheck on hits
            for (int r = 0; r < 8; r++) {
                float ar = sa28[ib + r];
                u64 ard = pack2(ar, ar);
                for (int s2 = 0; s2 < 4; s2++) {
                    u64 c2v = fma2r(acc[r][s2], NEG2, addx2(ard, bj2[s2]));
                    float clo, chi; unpack2(c2v, clo, chi);
                    if (clo < 0.5f) recheck(p, A, B, i0 + ib + r, j0 + jb + 2 * s2, a2, b2);
                    if (chi < 0.5f) recheck(p, A, B, i0 + ib + r, j0 + jb + 2 * s2 + 1, a2, b2);
                }
            }
        }
        __syncthreads();   // protect Bs before next tile's load
    }
}

// ---------------- single-barrier block sum (butterfly, double-buffered) ----------------
__device__ __forceinline__ float blockSumFast(float x, float* red, int call) {
    int lane = threadIdx.x & 31, w = threadIdx.x >> 5;
    int nw = blockDim.x >> 5;
#pragma unroll
    for (int o = 16; o; o >>= 1) x += __shfl_xor_sync(0xffffffffu, x, o);
    float* buf = red + (call & 1) * 32;
    if (lane == 0) buf[w] = x;
    __syncthreads();
    float y = (lane < nw) ? buf[lane] : 0.f;
#pragma unroll
    for (int o = 16; o; o >>= 1) y += __shfl_xor_sync(0xffffffffu, y, o);
    return y;   // all threads hold the total
}

// ---------------- Sinkhorn iterations, O(n) per iter; one block per pairing ----------------
__global__ void __launch_bounds__(1024, 1) k_iter() {
    int p = blockIdx.x;
    int t = threadIdx.x;                       // 1024 threads, 8 elems each
    const float* r2 = (p == 2) ? g_y2 : g_x2;  // row norms
    const float* c2 = (p == 0) ? g_y2 : ((p == 1) ? g_x2 : g_y2); // col norms

    float u[8], v[8], dk[8], dkc[8];
#pragma unroll
    for (int k = 0; k < 8; k++) {
        int i = t + k * 1024;
        v[k] = 1.f; u[k] = 1.f;
        dk[k]  = g_dk_diag[p][i];
        dkc[k] = g_dkc_diag[p][i];
    }
    int off = min(g_sp_cnt[p], SP_CAP);
    __shared__ float red[64];
    const float a = 1.f / NROW, b = 1.f / NROW, s = EPS_STAB;
    int call = 0;

    for (int it = 0; it < 100; it++) {
        // --- Kv, u update ---
        float lv = ((v[0] + v[1]) + (v[2] + v[3])) + ((v[4] + v[5]) + (v[6] + v[7]));
        float sv = blockSumFast(lv, red, call++);
        if (off) {
#pragma unroll
            for (int k = 0; k < 8; k++) { g_v[p][t + k * 1024] = v[k]; g_acc[p][t + k * 1024] = 0.f; }
            __syncthreads();
            for (int e = t; e < off; e += 1024)
                atomicAdd(&g_acc[p][g_sp_i[p][e]], g_sp_dk[p][e] * g_v[p][g_sp_j[p][e]]);
            __syncthreads();
        }
#pragma unroll
        for (int k = 0; k < 8; k++) {
            float kv = fmaf(dk[k], v[k], s * sv);
            if (off) kv += g_acc[p][t + k * 1024];
            u[k] = __fdividef(a, fmaxf(kv, s));
        }
        // --- K^T u, v update ---
        float lu = ((u[0] + u[1]) + (u[2] + u[3])) + ((u[4] + u[5]) + (u[6] + u[7]));
        float su = blockSumFast(lu, red, call++);
        if (off) {
#pragma unroll
            for (int k = 0; k < 8; k++) { g_u[p][t + k * 1024] = u[k]; g_acc[p][t + k * 1024] = 0.f; }
            __syncthreads();
            for (int e = t; e < off; e += 1024)
                atomicAdd(&g_acc[p][g_sp_j[p][e]], g_sp_dk[p][e] * g_u[p][g_sp_i[p][e]]);
            __syncthreads();
        }
#pragma unroll
        for (int k = 0; k < 8; k++) {
            float ku = fmaf(dk[k], u[k], s * su);
            if (off) ku += g_acc[p][t + k * 1024];
            v[k] = __fdividef(b, fmaxf(ku, s));
        }
    }

    // final scalar reductions + publish u,v
    float lsu = 0.f, lsv = 0.f, lux2 = 0.f, lvy2 = 0.f, ldc = 0.f;
#pragma unroll
    for (int k = 0; k < 8; k++) {
        int i = t + k * 1024;
        lsu += u[k]; lsv += v[k];
        lux2 = fmaf(u[k], r2[i], lux2);
        lvy2 = fmaf(v[k], c2[i], lvy2);
        ldc  = fmaf(dkc[k], u[k] * v[k], ldc);
        g_u[p][i] = u[k]; g_v[p][i] = v[k];
    }
    float rsu  = blockSumFast(lsu,  red, call++);
    float rsv  = blockSumFast(lsv,  red, call++);
    float rux2 = blockSumFast(lux2, red, call++);
    float rvy2 = blockSumFast(lvy2, red, call++);
    float rdc  = blockSumFast(ldc,  red, call++);
    if (t == 0) {
        g_scal[p][0] = rsu; g_scal[p][1] = rsv;
        g_scal[p][2] = rux2; g_scal[p][3] = rvy2; g_scal[p][4] = rdc;
    }
}

// ---------------- weighted column sums: X^T u and Y^T v per pairing ----------------
__global__ void k_colsum(const float* __restrict__ X, const float* __restrict__ Y) {
    int task = blockIdx.y;           // 0..5
    int p = task >> 1, side = task & 1;
    const float* M; const float* w;
    if (side == 0) { M = (p == 2) ? Y : X; w = g_u[p]; }
    else           { M = (p == 0) ? Y : ((p == 1) ? X : Y); w = g_v[p]; }
    int col = threadIdx.x;           // 128
    int r0 = blockIdx.x * (NROW / 16);
    float a0 = 0.f, a1 = 0.f, a2 = 0.f, a3 = 0.f;
    for (int r = r0; r < r0 + NROW / 16; r += 4) {
        a0 = fmaf(w[r + 0], M[(size_t)(r + 0) * D + col], a0);
        a1 = fmaf(w[r + 1], M[(size_t)(r + 1) * D + col], a1);
        a2 = fmaf(w[r + 2], M[(size_t)(r + 2) * D + col], a2);
        a3 = fmaf(w[r + 3], M[(size_t)(r + 3) * D + col], a3);
    }
    atomicAdd(&g_PQ[task][col], (a0 + a1) + (a2 + a3));
}

// ---------------- assemble costs and divergence ----------------
__global__ void k_final(float* __restrict__ out) {
    __shared__ float red[64];
    __shared__ float costs[3];
    int t = threadIdx.x;  // 128
    int call = 0;
    for (int p = 0; p < 3; p++) {
        float x = g_PQ[2 * p][t] * g_PQ[2 * p + 1][t];
        float pq = blockSumFast(x, red, call++);
        float oc = 0.f;
        int off = min(g_sp_cnt[p], SP_CAP);
        for (int e = t; e < off; e += 128)
            oc += g_sp_dkc[p][e] * g_u[p][g_sp_i[p][e]] * g_v[p][g_sp_j[p][e]];
        oc = blockSumFast(oc, red, call++);
        if (t == 0) {
            float su = g_scal[p][0], sv = g_scal[p][1];
            float ux2 = g_scal[p][2], vy2 = g_scal[p][3], dc = g_scal[p][4];
            float cost = EPS_STAB * (ux2 * sv + su * vy2 - 2.f * pq) + dc + oc;
            costs[p] = fmaxf(cost, 0.f);
        }
        __syncthreads();
    }
    if (t == 0) {
        float div = costs[0] - 0.5f * (costs[1] + costs[2]);
        out[0] = fminf(fmaxf(div, 0.f), 10000.f);
    }
}

// ---------------- launch ----------------
extern "C" void kernel_launch(void* const* d_in, const int* in_sizes, int n_in,
                              void* d_out, int out_size) {
    const float* X = (const float*)d_in[0];
    const float* Y = (const float*)d_in[1];
    float* out = (float*)d_out;
    (void)in_sizes; (void)n_in; (void)out_size;

    k_init<<<64, 256>>>();
    k_norms<<<(2 * NROW) / 8, 256>>>(X, Y);                    // one warp per row
    k_scan<<<(3 * 4096) / TPB_TILES, 256>>>(X, Y);             // 8 j-tiles per block
    k_iter<<<3, 1024>>>();                                     // one block per pairing
    k_colsum<<<dim3(16, 6), 128>>>(X, Y);
    k_final<<<1, 128>>>(out);
}